// round 4
// baseline (speedup 1.0000x reference)
#include <cuda_runtime.h>

// Persistent scratch (no device allocation allowed in kernel_launch)
__device__ double g_acc;

__global__ void zero_acc_kernel() { g_acc = 0.0; }

__global__ void __launch_bounds__(256)
bloom_loss_kernel(const float* __restrict__ inputs,
                  const int* __restrict__ targets,
                  int B /* rows */, int nquads /* B/4 rounded down */) {
    const float4* __restrict__ in4 = (const float4*)inputs;
    const int4* __restrict__ tg4 = (const int4*)targets;

    int t = blockIdx.x * blockDim.x + threadIdx.x;

    float local = 0.0f;

    if (t < nquads) {
        // 5 float4 = 20 floats = 4 rows of 5 classes, perfectly coalesced
        float4 v0 = in4[t * 5 + 0];
        float4 v1 = in4[t * 5 + 1];
        float4 v2 = in4[t * 5 + 2];
        float4 v3 = in4[t * 5 + 3];
        float4 v4 = in4[t * 5 + 4];
        int4 tg = tg4[t];

        float x[20] = {v0.x, v0.y, v0.z, v0.w,
                       v1.x, v1.y, v1.z, v1.w,
                       v2.x, v2.y, v2.z, v2.w,
                       v3.x, v3.y, v3.z, v3.w,
                       v4.x, v4.y, v4.z, v4.w};
        int tgt[4] = {tg.x, tg.y, tg.z, tg.w};

        #pragma unroll
        for (int r = 0; r < 4; r++) {
            int tt = tgt[r];
            // max over 5 (constant indices after unroll -> pure registers)
            float m = x[r * 5 + 0];
            #pragma unroll
            for (int j = 1; j < 5; j++) m = fmaxf(m, x[r * 5 + j]);

            float s = 0.0f, sumx = 0.0f, pen = 0.0f, xt = 0.0f;
            #pragma unroll
            for (int j = 0; j < 5; j++) {
                float xv = x[r * 5 + j];
                float e = __expf(xv - m);
                s += e;
                sumx += xv;
                int d = tt - j; d = d < 0 ? -d : d;
                float w = (d >= 3) ? 2.0f : 0.5f * (float)d;
                pen += e * w;
                xt = (j == tt) ? xv : xt;   // predicated select, no dynamic index
            }
            float lse = m + __logf(s);
            // label-smoothed CE: -(0.875*lp[t] + 0.025*sum(lp)) with lp = x - lse
            float ce = lse - 0.875f * xt - 0.025f * sumx;
            local += ce + 0.1f * (pen / s);
        }
    }

    // scalar tail rows (B not divisible by 4) handled by first threads of block 0
    int tail_start = nquads * 4;
    int tail = B - tail_start;
    if (blockIdx.x == 0 && threadIdx.x < (unsigned)tail) {
        int row = tail_start + threadIdx.x;
        int tt = targets[row];
        float xr[5];
        #pragma unroll
        for (int j = 0; j < 5; j++) xr[j] = inputs[row * 5 + j];
        float m = xr[0];
        #pragma unroll
        for (int j = 1; j < 5; j++) m = fmaxf(m, xr[j]);
        float s = 0.0f, sumx = 0.0f, pen = 0.0f, xt = 0.0f;
        #pragma unroll
        for (int j = 0; j < 5; j++) {
            float e = __expf(xr[j] - m);
            s += e; sumx += xr[j];
            int d = tt - j; d = d < 0 ? -d : d;
            float w = (d >= 3) ? 2.0f : 0.5f * (float)d;
            pen += e * w;
            xt = (j == tt) ? xr[j] : xt;
        }
        float lse = m + __logf(s);
        local += (lse - 0.875f * xt - 0.025f * sumx) + 0.1f * (pen / s);
    }

    // --- block reduction: warp shuffle -> shared -> one atomic per block ---
    #pragma unroll
    for (int off = 16; off > 0; off >>= 1)
        local += __shfl_xor_sync(0xFFFFFFFFu, local, off);

    __shared__ float warp_sums[8];
    int lane = threadIdx.x & 31;
    int wid = threadIdx.x >> 5;
    if (lane == 0) warp_sums[wid] = local;
    __syncthreads();

    if (wid == 0) {
        float v = (lane < (blockDim.x >> 5)) ? warp_sums[lane] : 0.0f;
        #pragma unroll
        for (int off = 4; off > 0; off >>= 1)
            v += __shfl_xor_sync(0xFFFFFFFFu, v, off);
        if (lane == 0) atomicAdd(&g_acc, (double)v);
    }
}

__global__ void finalize_kernel(float* __restrict__ out, double invB) {
    out[0] = (float)(g_acc * invB);
}

extern "C" void kernel_launch(void* const* d_in, const int* in_sizes, int n_in,
                              void* d_out, int out_size) {
    const float* inputs = (const float*)d_in[0];
    const int* targets = (const int*)d_in[1];
    float* out = (float*)d_out;

    int B = in_sizes[1];          // targets element count = number of rows
    int nquads = B / 4;

    zero_acc_kernel<<<1, 1>>>();

    int threads = 256;
    int blocks = (nquads + threads - 1) / threads;
    if (blocks < 1) blocks = 1;
    bloom_loss_kernel<<<blocks, threads>>>(inputs, targets, B, nquads);

    finalize_kernel<<<1, 1>>>(out, 1.0 / (double)B);
}